// round 9
// baseline (speedup 1.0000x reference)
#include <cuda_runtime.h>
#include <cuda_fp16.h>
#include <cstdint>

#define D        128
#define NTEST    4096
#define NTRAIN   16384
#define TM       64
#define TN       128
#define MTILES   (NTEST / TM)       // 64
#define NTILES   (NTRAIN / TN)      // 128
#define NJOBS    (MTILES * NTILES)  // 8192
#define NTHREADS 128                // 4 warps, warp tile 32x64

// ---------------- device scratch (zero-initialized at module load) ----------------
__device__ double g_colsum[D];
__device__ double g_colsumsq[D];
__device__ float  g_inv_bw[D];
__device__ float  g_Z;
__device__ __half g_Ah1[NTEST * D];
__device__ __half g_Ah2[NTEST * D];
__device__ __half g_Bh1[NTRAIN * D];
__device__ __half g_Bh2[NTRAIN * D];
__device__ float  g_tnorm[NTEST];
__device__ float  g_trnorm[NTRAIN];

// ---------------- helpers ----------------
__device__ __forceinline__ uint32_t smem_u32(const void* p) {
    uint32_t a;
    asm("{ .reg .u64 t; cvta.to.shared.u64 t, %1; cvt.u32.u64 %0, t; }" : "=r"(a) : "l"(p));
    return a;
}
__device__ __forceinline__ void cp16s(uint32_t dst, const void* src) {
    asm volatile("cp.async.cg.shared.global [%0], [%1], 16;" :: "r"(dst), "l"(src));
}
__device__ __forceinline__ float ex2(float x) {
    float r; asm("ex2.approx.ftz.f32 %0, %1;" : "=f"(r) : "f"(x)); return r;
}
__device__ __forceinline__ void ldsm_x4(uint32_t (&r)[4], uint32_t addr) {
    asm volatile("ldmatrix.sync.aligned.m8n8.x4.shared.b16 {%0,%1,%2,%3}, [%4];"
                 : "=r"(r[0]), "=r"(r[1]), "=r"(r[2]), "=r"(r[3]) : "r"(addr));
}
__device__ __forceinline__ void mma16816(float (&d)[4], const uint32_t (&a)[4],
                                         uint32_t b0, uint32_t b1) {
    asm volatile("mma.sync.aligned.m16n8k16.row.col.f32.f16.f16.f32 "
                 "{%0,%1,%2,%3}, {%4,%5,%6,%7}, {%8,%9}, {%0,%1,%2,%3};"
                 : "+f"(d[0]), "+f"(d[1]), "+f"(d[2]), "+f"(d[3])
                 : "r"(a[0]), "r"(a[1]), "r"(a[2]), "r"(a[3]), "r"(b0), "r"(b1));
}

// ---------------- SMEM layout (per block) ----------------
// A:   [0, 32768)       limb0 16K | limb1 16K  (64 rows x 256B, XOR swizzle)
// B:   [32768, 98304)   limb0 32K | limb1 32K  (128 rows, single-buffered)
// TRN: [98304, 99328)   2 x 512B (double-buffered)
#define SM_A     0
#define SM_B     32768
#define SM_TRN   98304
#define SM_TOTAL 99328

// -------- launch 1: per-column sum / sumsq over train --------
__global__ void k_colstats(const float* __restrict__ train) {
    const int warp = threadIdx.x >> 5, lane = threadIdx.x & 31;
    const int c4 = lane * 4;
    double s[4] = {0, 0, 0, 0}, s2[4] = {0, 0, 0, 0};
    const int rbase = blockIdx.x * 128 + warp;
#pragma unroll 4
    for (int i = 0; i < 16; ++i) {
        float4 v = *(const float4*)(train + (size_t)(rbase + i * 8) * D + c4);
        s[0] += v.x; s2[0] += (double)v.x * v.x;
        s[1] += v.y; s2[1] += (double)v.y * v.y;
        s[2] += v.z; s2[2] += (double)v.z * v.z;
        s[3] += v.w; s2[3] += (double)v.w * v.w;
    }
    __shared__ double sh[2][8][D];
#pragma unroll
    for (int j = 0; j < 4; ++j) { sh[0][warp][c4 + j] = s[j]; sh[1][warp][c4 + j] = s2[j]; }
    __syncthreads();
    if (threadIdx.x < D) {
        const int c = threadIdx.x;
        double a = 0, b2 = 0;
#pragma unroll
        for (int w = 0; w < 8; ++w) { a += sh[0][w][c]; b2 += sh[1][w][c]; }
        atomicAdd(&g_colsum[c], a);
        atomicAdd(&g_colsumsq[c], b2);
    }
}

// -------- launch 2: bandwidth + Z; re-arm state; zero out --------
__global__ void k_finalize(float* __restrict__ out) {
    int c = threadIdx.x;
    const double n = (double)NTRAIN;
    double mean = g_colsum[c] / n;
    double var  = (g_colsumsq[c] - n * mean * mean) / (n - 1.0);
    double sd   = sqrt(fmax(var, 0.0));
    sd = fmax(sd, 0.01);
    double bw = 1.06 * sd * exp(-log(n) / (4.0 + (double)D));
    bw = fmin(bw, 0.49);
    g_inv_bw[c] = (float)(1.0 / bw);

    __shared__ double red[D];
    red[c] = log(bw);
    __syncthreads();
    for (int off = 64; off; off >>= 1) {
        if (c < off) red[c] += red[c + off];
        __syncthreads();
    }
    if (c == 0) {
        double Z = 0.5 * (double)D * log(2.0 * 3.14159265358979323846) + red[0] + log(n);
        g_Z = (float)Z;
    }
    g_colsum[c] = 0.0;
    g_colsumsq[c] = 0.0;
    for (int i = c; i < NTEST; i += 128) out[i] = 0.f;
}

// -------- launch 3: scale, fp16 two-limb split, norms --------
__global__ void k_split(const float* __restrict__ test, const float* __restrict__ train) {
    const int lane = threadIdx.x & 31;
    const int r = blockIdx.x * 8 + (threadIdx.x >> 5);
    const float* src; __half *d1, *d2; float* nrm; int rr = r;
    if (r < NTEST) { src = test;  d1 = g_Ah1; d2 = g_Ah2; nrm = g_tnorm; }
    else { rr = r - NTEST; src = train; d1 = g_Bh1; d2 = g_Bh2; nrm = g_trnorm; }

    const int c4 = lane * 4;
    float4 v = *(const float4*)(src + (size_t)rr * D + c4);
    float4 w = *(const float4*)(g_inv_bw + c4);
    v.x *= w.x; v.y *= w.y; v.z *= w.z; v.w *= w.w;

    __half2 p1a = __floats2half2_rn(v.x, v.y);
    __half2 p1b = __floats2half2_rn(v.z, v.w);
    float2 f1a = __half22float2(p1a), f1b = __half22float2(p1b);
    __half2 p2a = __floats2half2_rn(v.x - f1a.x, v.y - f1a.y);
    __half2 p2b = __floats2half2_rn(v.z - f1b.x, v.w - f1b.y);

    *(__half2*)(d1 + (size_t)rr * D + c4)     = p1a;
    *(__half2*)(d1 + (size_t)rr * D + c4 + 2) = p1b;
    *(__half2*)(d2 + (size_t)rr * D + c4)     = p2a;
    *(__half2*)(d2 + (size_t)rr * D + c4 + 2) = p2b;

    float s = v.x * v.x + v.y * v.y + v.z * v.z + v.w * v.w;
#pragma unroll
    for (int off = 16; off; off >>= 1) s += __shfl_xor_sync(0xffffffffu, s, off);
    if (lane == 0) nrm[rr] = s;
}

// -------- launch 4: persistent HMMA split-fp16 GEMM + fused KDE epilogue --------
// 4 warps, warp tile 32x64; 2 blocks/SM overlap epilogue with MMA; register epilogue.
extern __shared__ char smem[];

__global__ void __launch_bounds__(NTHREADS, 2) k_main(float* __restrict__ out) {
    const uint32_t sb = smem_u32(smem);
    const int tid = threadIdx.x, lane = tid & 31, wid = tid >> 5;
    const int wm = wid & 1, wn = wid >> 1;   // warp tile: rows wm*32, cols wn*64
    const int qr = lane >> 2, qc = lane & 3;

    const int G = gridDim.x, b = blockIdx.x;
    const int per = NJOBS / G, rem = NJOBS % G;
    const int lo = b * per + min(b, rem);
    const int nloc = per + (b < rem ? 1 : 0);
    if (nloc <= 0) return;

    const float Zf = g_Z;
    const float c0v = -0.72134752f / Zf;  // -0.5*log2(e)/Z
    const float c1v = -1.44269504f;       // -log2(e)

    int rowid[4];
#pragma unroll
    for (int i = 0; i < 4; ++i) rowid[i] = wm * 32 + (i >> 1) * 16 + (i & 1) * 8 + qr;

    const int arow = wm * 32 + (lane & 15);
    const int akg  = lane >> 4;
    const int nofs = (lane & 7) + ((lane >> 4) << 3);
    const int bkg  = (lane >> 3) & 1;

    auto loadA = [&](int mbase) {
        for (int i = tid; i < 2048; i += NTHREADS) {
            int l = i >> 10, idx = i & 1023;
            int r = idx >> 4, g = idx & 15;
            const __half* src = (l ? g_Ah2 : g_Ah1) + (size_t)(mbase + r) * D + g * 8;
            cp16s(sb + SM_A + l * 16384 + (uint32_t)(r * 256 + ((g ^ (r & 7)) << 4)), src);
        }
        asm volatile("cp.async.commit_group;" ::: "memory");
        asm volatile("cp.async.wait_all;" ::: "memory");
        __syncthreads();
    };
    // single-buffered B (64KB: 128 rows x 2 limbs); trn double-buffered
    auto loadB = [&](int nt, int tbuf) {
        int nbase = nt * TN;
        for (int i = tid; i < 4096; i += NTHREADS) {
            int l = i >> 11, idx = i & 2047;
            int r = idx >> 4, g = idx & 15;
            const __half* src = (l ? g_Bh2 : g_Bh1) + (size_t)(nbase + r) * D + g * 8;
            cp16s(sb + SM_B + l * 32768 + (uint32_t)(r * 256 + ((g ^ (r & 7)) << 4)), src);
        }
        if (tid < 32)
            cp16s(sb + SM_TRN + tbuf * 512 + tid * 16, g_trnorm + nbase + tid * 4);
        asm volatile("cp.async.commit_group;" ::: "memory");
    };

    float acc[2][8][4];
    float accR[4] = {0.f, 0.f, 0.f, 0.f};
    float tnr[4];

    int cur_m = lo >> 7;   // / NTILES
    loadA(cur_m * TM);
    loadB(lo & (NTILES - 1), 0);
#pragma unroll
    for (int i = 0; i < 4; ++i) tnr[i] = g_tnorm[cur_m * TM + rowid[i]];

    for (int t = 0; t < nloc; ++t) {
        const int job = lo + t;
        const int mt = job >> 7;

        if (mt != cur_m) {
            if (qc == 0) {
#pragma unroll
                for (int i = 0; i < 4; ++i) {
                    atomicAdd(&out[cur_m * TM + rowid[i]], accR[i]);
                    accR[i] = 0.f;
                }
            } else {
#pragma unroll
                for (int i = 0; i < 4; ++i) accR[i] = 0.f;
            }
            __syncthreads();
            loadA(mt * TM);   // wait_all inside also drains pending B prefetch
            cur_m = mt;
#pragma unroll
            for (int i = 0; i < 4; ++i) tnr[i] = g_tnorm[cur_m * TM + rowid[i]];
        }

        asm volatile("cp.async.wait_group 0;" ::: "memory");
        __syncthreads();   // B(t) + trn(t) ready

#pragma unroll
        for (int im = 0; im < 2; ++im)
#pragma unroll
            for (int jn = 0; jn < 8; ++jn)
#pragma unroll
                for (int e = 0; e < 4; ++e) acc[im][jn][e] = 0.f;

        const uint32_t A0 = sb + SM_A, A1 = A0 + 16384;
        const uint32_t B0 = sb + SM_B, B1 = B0 + 32768;

        // fused 3-limb mainloop: acc += A0*B0 + A0*B1 + A1*B0
#pragma unroll
        for (int ks = 0; ks < 8; ++ks) {
            const int ga = ks * 2 + akg, gb = ks * 2 + bkg;
            uint32_t a0[2][4], a1[2][4];
#pragma unroll
            for (int im = 0; im < 2; ++im) {
                int row = arow + im * 16;
                uint32_t off = (uint32_t)(row * 256 + ((ga ^ (row & 7)) << 4));
                ldsm_x4(a0[im], A0 + off);
                ldsm_x4(a1[im], A1 + off);
            }
            uint32_t b0f[4][4], b1f[4][4];
#pragma unroll
            for (int j = 0; j < 4; ++j) {
                int row = wn * 64 + j * 16 + nofs;
                uint32_t off = (uint32_t)(row * 256 + ((gb ^ (row & 7)) << 4));
                ldsm_x4(b0f[j], B0 + off);
                ldsm_x4(b1f[j], B1 + off);
            }
#pragma unroll
            for (int im = 0; im < 2; ++im)
#pragma unroll
                for (int jn = 0; jn < 8; ++jn) {
                    uint32_t l0 = b0f[jn >> 1][(jn & 1) * 2], h0 = b0f[jn >> 1][(jn & 1) * 2 + 1];
                    uint32_t l1 = b1f[jn >> 1][(jn & 1) * 2], h1 = b1f[jn >> 1][(jn & 1) * 2 + 1];
                    mma16816(acc[im][jn], a0[im], l0, h0);
                    mma16816(acc[im][jn], a0[im], l1, h1);
                    mma16816(acc[im][jn], a1[im], l0, h0);
                }
        }

        __syncthreads();   // all warps done reading B(t)
        if (t + 1 < nloc) loadB((job + 1) & (NTILES - 1), (t + 1) & 1);  // overlaps epilogue

        // fused register epilogue (trn buf t&1)
        const float* trn = (const float*)(smem + SM_TRN + (t & 1) * 512);
#pragma unroll
        for (int im = 0; im < 2; ++im)
#pragma unroll
            for (int h = 0; h < 2; ++h) {
                float s = 0.f;
                const float tv = tnr[im * 2 + h];
#pragma unroll
                for (int jn = 0; jn < 8; ++jn) {
                    int n0 = wn * 64 + jn * 8 + qc * 2;
                    float d0 = acc[im][jn][2 * h], d1 = acc[im][jn][2 * h + 1];
                    float s0 = fmaxf(fmaf(-2.f, d0, tv + trn[n0]), 0.f);
                    float s1 = fmaxf(fmaf(-2.f, d1, tv + trn[n0 + 1]), 0.f);
                    s += ex2(fmaf(s0, c0v, c1v));
                    s += ex2(fmaf(s1, c0v, c1v));
                }
                s += __shfl_xor_sync(0xffffffffu, s, 1);
                s += __shfl_xor_sync(0xffffffffu, s, 2);
                if (qc == 0) accR[im * 2 + h] += s;
            }
    }

    if (qc == 0) {
#pragma unroll
        for (int i = 0; i < 4; ++i)
            atomicAdd(&out[cur_m * TM + rowid[i]], accR[i]);
    }
}

extern "C" void kernel_launch(void* const* d_in, const int* in_sizes, int n_in,
                              void* d_out, int out_size) {
    const float* test  = (const float*)d_in[0];
    const float* train = (const float*)d_in[1];
    float* out = (float*)d_out;
    (void)in_sizes; (void)n_in; (void)out_size;

    int dev = 0;
    cudaGetDevice(&dev);
    int smc = 148;
    cudaDeviceGetAttribute(&smc, cudaDevAttrMultiProcessorCount, dev);

    cudaFuncSetAttribute(k_main, cudaFuncAttributeMaxDynamicSharedMemorySize, SM_TOTAL);

    k_colstats<<<128, 256>>>(train);
    k_finalize<<<1, 128>>>(out);
    k_split<<<(NTEST + NTRAIN) / 8, 256>>>(test, train);
    k_main<<<2 * smc, NTHREADS, SM_TOTAL>>>(out);
}